// round 1
// baseline (speedup 1.0000x reference)
#include <cuda_runtime.h>

#define ND 32
#define MAXN 100000
#define MAXE 1600000

static constexpr size_t SLOT = (size_t)MAXN * ND;

// One big scratch arena (no allocations allowed).
// Layout (floats): acc,T,X1,X2,h1,h2,fs,fd,ft (9 * SLOT), logits(E), ex(E),
// then node scalars: deg(int,N), segmax(uint,N), denom(N), dinv(N)
__device__ float g_buf[9 * SLOT + 2 * (size_t)MAXE + 4 * (size_t)MAXN];

// ---------------------------------------------------------------------------
// helpers
// ---------------------------------------------------------------------------
__device__ __forceinline__ unsigned enc_f(float f) {
    unsigned b = __float_as_uint(f);
    return (b & 0x80000000u) ? ~b : (b | 0x80000000u);
}
__device__ __forceinline__ float dec_f(unsigned k) {
    return (k & 0x80000000u) ? __uint_as_float(k & 0x7fffffffu)
                             : __uint_as_float(~k);
}
__device__ __forceinline__ float leaky(float x, float s) {
    return x > 0.0f ? x : s * x;
}

// ---------------------------------------------------------------------------
// kernels
// ---------------------------------------------------------------------------
__global__ void k_zero(float* __restrict__ p, int n) {
    int i = blockIdx.x * blockDim.x + threadIdx.x;
    if (i < n) p[i] = 0.0f;
}

__global__ void k_deg(const int* __restrict__ dst, int* __restrict__ deg, int E) {
    int e = blockIdx.x * blockDim.x + threadIdx.x;
    if (e < E) atomicAdd(&deg[dst[e]], 1);
}

__global__ void k_dinv(const int* __restrict__ deg, float* __restrict__ dinv, int n) {
    int i = blockIdx.x * blockDim.x + threadIdx.x;
    if (i < n) dinv[i] = rsqrtf(fmaxf((float)deg[i], 1.0f));
}

// T = f * dinv (broadcast per node row)
__global__ void k_prescale(const float* __restrict__ f, const float* __restrict__ dinv,
                           float* __restrict__ T, int n) {
    int i = blockIdx.x * blockDim.x + threadIdx.x;
    if (i < n * ND) T[i] = f[i] * dinv[i >> 5];
}

// acc[dst] += T[src]   (warp per edge, lane per feature dim)
__global__ void k_gather(const int* __restrict__ src, const int* __restrict__ dst,
                         const float* __restrict__ T, float* __restrict__ acc, int E) {
    long t = (long)blockIdx.x * blockDim.x + threadIdx.x;
    int e = (int)(t >> 5);
    if (e >= E) return;
    int lane = (int)(t & 31);
    int s = src[e], d = dst[e];
    atomicAdd(&acc[d * ND + lane], T[s * ND + lane]);
}

// X1 = -r*acc*dinv + (r-1)*f ;  T = X1*dinv
__global__ void k_X1(const float* __restrict__ acc, const float* __restrict__ f,
                     const float* __restrict__ dinv, const float* __restrict__ lam,
                     float* __restrict__ X1, float* __restrict__ T, int n) {
    int i = blockIdx.x * blockDim.x + threadIdx.x;
    if (i >= n * ND) return;
    float r = 2.0f / lam[0];
    float dv = dinv[i >> 5];
    float x1 = -r * acc[i] * dv + (r - 1.0f) * f[i];
    X1[i] = x1;
    T[i] = x1 * dv;
}

// X2 = -2r*acc*dinv + 2(r-1)*X1 - f
__global__ void k_X2(const float* __restrict__ acc, const float* __restrict__ X1,
                     const float* __restrict__ f, const float* __restrict__ dinv,
                     const float* __restrict__ lam, float* __restrict__ X2, int n) {
    int i = blockIdx.x * blockDim.x + threadIdx.x;
    if (i >= n * ND) return;
    float r = 2.0f / lam[0];
    float dv = dinv[i >> 5];
    X2[i] = -2.0f * r * acc[i] * dv + 2.0f * (r - 1.0f) * X1[i] - f[i];
}

// out = leaky_relu([X0,X1,X2] @ W + b, 0.01); optionally Tout = out*dinv
__global__ void k_cheb_linear(const float* __restrict__ X0, const float* __restrict__ X1,
                              const float* __restrict__ X2, const float* __restrict__ W,
                              const float* __restrict__ b, const float* __restrict__ dinv,
                              float* __restrict__ out, float* __restrict__ Tout, int n) {
    __shared__ float sW[96 * 32];
    __shared__ float sb[32];
    int t = threadIdx.y * 32 + threadIdx.x;
    for (int i = t; i < 96 * 32; i += 256) sW[i] = W[i];
    if (t < 32) sb[t] = b[t];
    __syncthreads();
    int node = blockIdx.x * 8 + threadIdx.y;
    if (node >= n) return;
    int col = threadIdx.x;
    float s = sb[col];
    const float* x0 = X0 + node * ND;
    const float* x1 = X1 + node * ND;
    const float* x2 = X2 + node * ND;
#pragma unroll
    for (int j = 0; j < 32; j++) s += x0[j] * sW[j * 32 + col];
#pragma unroll
    for (int j = 0; j < 32; j++) s += x1[j] * sW[(32 + j) * 32 + col];
#pragma unroll
    for (int j = 0; j < 32; j++) s += x2[j] * sW[(64 + j) * 32 + col];
    s = leaky(s, 0.01f);
    out[node * ND + col] = s;
    if (Tout) Tout[node * ND + col] = s * dinv[node];
}

// fs = h@Ws+bs ; fd = h@Wd+bd   (H=1, D=32)
__global__ void k_fsfd(const float* __restrict__ h, const float* __restrict__ Ws,
                       const float* __restrict__ bs, const float* __restrict__ Wd,
                       const float* __restrict__ bd, float* __restrict__ fs,
                       float* __restrict__ fd, int n) {
    __shared__ float sWs[32 * 32], sWd[32 * 32], sbs[32], sbd[32];
    int t = threadIdx.y * 32 + threadIdx.x;
    for (int i = t; i < 1024; i += 256) { sWs[i] = Ws[i]; sWd[i] = Wd[i]; }
    if (t < 32) { sbs[t] = bs[t]; sbd[t] = bd[t]; }
    __syncthreads();
    int node = blockIdx.x * 8 + threadIdx.y;
    if (node >= n) return;
    int col = threadIdx.x;
    float a = sbs[col], c = sbd[col];
    const float* hr = h + node * ND;
#pragma unroll
    for (int j = 0; j < 32; j++) {
        float x = hr[j];
        a += x * sWs[j * 32 + col];
        c += x * sWd[j * 32 + col];
    }
    fs[node * ND + col] = a;
    fd[node * ND + col] = c;
}

// logits[e] = sum_d leaky(fs[src]+fd[dst],0.2)*attn[d]; segmax via encoded atomicMax
__global__ void k_logits(const int* __restrict__ src, const int* __restrict__ dst,
                         const float* __restrict__ fs, const float* __restrict__ fd,
                         const float* __restrict__ attn, float* __restrict__ logits,
                         unsigned* __restrict__ segmax, int E) {
    long t = (long)blockIdx.x * blockDim.x + threadIdx.x;
    int e = (int)(t >> 5);
    if (e >= E) return;
    int lane = (int)(t & 31);
    int s = src[e], d = dst[e];
    float v = fs[s * ND + lane] + fd[d * ND + lane];
    v = leaky(v, 0.2f);
    v *= attn[lane];
#pragma unroll
    for (int o = 16; o; o >>= 1) v += __shfl_down_sync(0xffffffffu, v, o);
    if (lane == 0) {
        logits[e] = v;
        atomicMax(&segmax[d], enc_f(v));
    }
}

// ex[e] = exp(logits[e]-m[dst]); denom[dst] += ex
__global__ void k_exp(const int* __restrict__ dst, const float* __restrict__ logits,
                      const unsigned* __restrict__ segmax, float* __restrict__ ex,
                      float* __restrict__ denom, int E) {
    int e = blockIdx.x * blockDim.x + threadIdx.x;
    if (e >= E) return;
    int d = dst[e];
    float m = dec_f(segmax[d]);
    float v = expf(logits[e] - m);
    ex[e] = v;
    atomicAdd(&denom[d], v);
}

// ft[dst] += fs[src] * (ex[e]/denom[dst])
__global__ void k_aggr(const int* __restrict__ src, const int* __restrict__ dst,
                       const float* __restrict__ fs, const float* __restrict__ ex,
                       const float* __restrict__ denom, float* __restrict__ ft, int E) {
    long t = (long)blockIdx.x * blockDim.x + threadIdx.x;
    int e = (int)(t >> 5);
    if (e >= E) return;
    int lane = (int)(t & 31);
    int s = src[e], d = dst[e];
    float a = ex[e] / denom[d];
    atomicAdd(&ft[d * ND + lane], fs[s * ND + lane] * a);
}

__global__ void k_out(const float* __restrict__ ft, float* __restrict__ out, int n) {
    int i = blockIdx.x * blockDim.x + threadIdx.x;
    if (i < n * ND) out[i] = leaky(ft[i], 0.01f);
}

// ---------------------------------------------------------------------------
// launch
// ---------------------------------------------------------------------------
extern "C" void kernel_launch(void* const* d_in, const int* in_sizes, int n_in,
                              void* d_out, int out_size) {
    const int*   src  = (const int*)d_in[0];
    const int*   dst  = (const int*)d_in[1];
    const float* emb  = (const float*)d_in[2];
    const float* lam  = (const float*)d_in[3];
    const float* chW  = (const float*)d_in[4];
    const float* chb  = (const float*)d_in[5];
    const float* Ws   = (const float*)d_in[6];
    const float* bs   = (const float*)d_in[7];
    const float* Wd   = (const float*)d_in[8];
    const float* bd   = (const float*)d_in[9];
    const float* attn = (const float*)d_in[10];

    const int E = in_sizes[0];
    const int n = in_sizes[2] / ND;

    float* base = nullptr;
    cudaGetSymbolAddress((void**)&base, g_buf);

    float* acc    = base;
    float* T      = base + 1 * SLOT;
    float* X1     = base + 2 * SLOT;
    float* X2     = base + 3 * SLOT;
    float* h1     = base + 4 * SLOT;
    float* h2     = base + 5 * SLOT;
    float* fs     = base + 6 * SLOT;
    float* fd     = base + 7 * SLOT;
    float* ft     = base + 8 * SLOT;
    float* logits = base + 9 * SLOT;
    float* exb    = logits + MAXE;
    float* nodes  = exb + MAXE;
    int*      deg    = (int*)nodes;
    unsigned* segmax = (unsigned*)(nodes + MAXN);
    float*    denom  = nodes + 2 * MAXN;
    float*    dinv   = nodes + 3 * MAXN;

    const int nt = 256;
    auto g = [&](long x) { return (int)((x + nt - 1) / nt); };
    const int gNode = g((long)n * ND);
    const int gEdgeW = g((long)E * ND);   // warp per edge
    const int gEdge  = g((long)E);
    const int gLin   = (n + 7) / 8;
    dim3 blin(32, 8);

    // --- degrees ---
    k_zero<<<g(3 * MAXN), nt>>>(nodes, 3 * MAXN);          // deg, segmax, denom
    k_deg<<<gEdge, nt>>>(dst, deg, E);
    k_dinv<<<g(n), nt>>>(deg, dinv, n);

    // --- ChebConv 1 (input = embedding) ---
    k_prescale<<<gNode, nt>>>(emb, dinv, T, n);
    k_zero<<<gNode, nt>>>(acc, n * ND);
    k_gather<<<gEdgeW, nt>>>(src, dst, T, acc, E);
    k_X1<<<gNode, nt>>>(acc, emb, dinv, lam, X1, T, n);
    k_zero<<<gNode, nt>>>(acc, n * ND);
    k_gather<<<gEdgeW, nt>>>(src, dst, T, acc, E);
    k_X2<<<gNode, nt>>>(acc, X1, emb, dinv, lam, X2, n);
    k_cheb_linear<<<gLin, blin>>>(emb, X1, X2, chW, chb, dinv, h1, T, n); // T = h1*dinv

    // --- ChebConv 2 (input = h1; T already = h1*dinv) ---
    k_zero<<<gNode, nt>>>(acc, n * ND);
    k_gather<<<gEdgeW, nt>>>(src, dst, T, acc, E);
    k_X1<<<gNode, nt>>>(acc, h1, dinv, lam, X1, T, n);
    k_zero<<<gNode, nt>>>(acc, n * ND);
    k_gather<<<gEdgeW, nt>>>(src, dst, T, acc, E);
    k_X2<<<gNode, nt>>>(acc, X1, h1, dinv, lam, X2, n);
    k_cheb_linear<<<gLin, blin>>>(h1, X1, X2, chW, chb, dinv, h2, nullptr, n);

    // --- GATv2 ---
    k_fsfd<<<gLin, blin>>>(h2, Ws, bs, Wd, bd, fs, fd, n);
    k_zero<<<gNode, nt>>>(ft, n * ND);
    k_logits<<<gEdgeW, nt>>>(src, dst, fs, fd, attn, logits, segmax, E);
    k_exp<<<gEdge, nt>>>(dst, logits, segmax, exb, denom, E);
    k_aggr<<<gEdgeW, nt>>>(src, dst, fs, exb, denom, ft, E);
    k_out<<<gNode, nt>>>(ft, (float*)d_out, n);
}

// round 2
// speedup vs baseline: 2.0713x; 2.0713x over previous
#include <cuda_runtime.h>

#define ND 32
#define MAXN 100000
#define MAXE 1600000

static constexpr size_t SLOT = (size_t)MAXN * ND;

// One big scratch arena (no allocations allowed).
__device__ float g_buf[9 * SLOT + 2 * (size_t)MAXE + 4 * (size_t)MAXN];

// ---------------------------------------------------------------------------
// helpers
// ---------------------------------------------------------------------------
__device__ __forceinline__ unsigned enc_f(float f) {
    unsigned b = __float_as_uint(f);
    return (b & 0x80000000u) ? ~b : (b | 0x80000000u);
}
__device__ __forceinline__ float dec_f(unsigned k) {
    return (k & 0x80000000u) ? __uint_as_float(k & 0x7fffffffu)
                             : __uint_as_float(~k);
}
__device__ __forceinline__ float leaky(float x, float s) {
    return x > 0.0f ? x : s * x;
}
__device__ __forceinline__ void red_v4(float* p, float4 v) {
    asm volatile("red.global.add.v4.f32 [%0], {%1,%2,%3,%4};"
                 :: "l"(p), "f"(v.x), "f"(v.y), "f"(v.z), "f"(v.w) : "memory");
}

// ---------------------------------------------------------------------------
// kernels
// ---------------------------------------------------------------------------
__global__ void k_zero(float* __restrict__ p, int n) {
    int i = blockIdx.x * blockDim.x + threadIdx.x;
    if (i < n) p[i] = 0.0f;
}

__global__ void k_deg(const int* __restrict__ dst, int* __restrict__ deg, int E) {
    int e = blockIdx.x * blockDim.x + threadIdx.x;
    if (e < E) atomicAdd(&deg[dst[e]], 1);
}

__global__ void k_dinv(const int* __restrict__ deg, float* __restrict__ dinv, int n) {
    int i = blockIdx.x * blockDim.x + threadIdx.x;
    if (i < n) dinv[i] = rsqrtf(fmaxf((float)deg[i], 1.0f));
}

// T = f * dinv ; acc = 0       (float4 lanes: 8 per node)
__global__ void k_prescale(const float4* __restrict__ f, const float* __restrict__ dinv,
                           float4* __restrict__ T, float4* __restrict__ acc, int n) {
    int i = blockIdx.x * blockDim.x + threadIdx.x;
    if (i >= n * 8) return;
    float dv = dinv[i >> 3];
    float4 v = f[i];
    v.x *= dv; v.y *= dv; v.z *= dv; v.w *= dv;
    T[i] = v;
    acc[i] = make_float4(0.f, 0.f, 0.f, 0.f);
}

// acc[dst] += T[src]   (8 threads per edge, float4 per thread, vector RED)
__global__ void k_gather(const int* __restrict__ src, const int* __restrict__ dst,
                         const float4* __restrict__ T, float* __restrict__ acc, int E) {
    long t = (long)blockIdx.x * blockDim.x + threadIdx.x;
    int e = (int)(t >> 3);
    if (e >= E) return;
    int lane = (int)(t & 7);
    int s = src[e], d = dst[e];
    float4 v = T[(size_t)s * 8 + lane];
    red_v4(acc + (size_t)d * ND + lane * 4, v);
}

// X1 = -r*acc*dinv + (r-1)*f ;  T = X1*dinv ; acc = 0
__global__ void k_X1(float4* __restrict__ acc, const float4* __restrict__ f,
                     const float* __restrict__ dinv, const float* __restrict__ lam,
                     float4* __restrict__ X1, float4* __restrict__ T, int n) {
    int i = blockIdx.x * blockDim.x + threadIdx.x;
    if (i >= n * 8) return;
    float r = 2.0f / lam[0];
    float dv = dinv[i >> 3];
    float4 a = acc[i], x = f[i], o, tt;
    o.x = -r * a.x * dv + (r - 1.0f) * x.x;
    o.y = -r * a.y * dv + (r - 1.0f) * x.y;
    o.z = -r * a.z * dv + (r - 1.0f) * x.z;
    o.w = -r * a.w * dv + (r - 1.0f) * x.w;
    X1[i] = o;
    tt.x = o.x * dv; tt.y = o.y * dv; tt.z = o.z * dv; tt.w = o.w * dv;
    T[i] = tt;
    acc[i] = make_float4(0.f, 0.f, 0.f, 0.f);
}

// X2 = -2r*acc*dinv + 2(r-1)*X1 - f ; acc = 0
__global__ void k_X2(float4* __restrict__ acc, const float4* __restrict__ X1,
                     const float4* __restrict__ f, const float* __restrict__ dinv,
                     const float* __restrict__ lam, float4* __restrict__ X2, int n) {
    int i = blockIdx.x * blockDim.x + threadIdx.x;
    if (i >= n * 8) return;
    float r = 2.0f / lam[0];
    float dv = dinv[i >> 3];
    float4 a = acc[i], x1 = X1[i], x0 = f[i], o;
    o.x = -2.0f * r * a.x * dv + 2.0f * (r - 1.0f) * x1.x - x0.x;
    o.y = -2.0f * r * a.y * dv + 2.0f * (r - 1.0f) * x1.y - x0.y;
    o.z = -2.0f * r * a.z * dv + 2.0f * (r - 1.0f) * x1.z - x0.z;
    o.w = -2.0f * r * a.w * dv + 2.0f * (r - 1.0f) * x1.w - x0.w;
    X2[i] = o;
    acc[i] = make_float4(0.f, 0.f, 0.f, 0.f);
}

// out = leaky_relu([X0,X1,X2] @ W + b, 0.01); optionally Tout = out*dinv
__global__ void k_cheb_linear(const float* __restrict__ X0, const float* __restrict__ X1,
                              const float* __restrict__ X2, const float* __restrict__ W,
                              const float* __restrict__ b, const float* __restrict__ dinv,
                              float* __restrict__ out, float* __restrict__ Tout, int n) {
    __shared__ float sW[96 * 32];
    __shared__ float sb[32];
    int t = threadIdx.y * 32 + threadIdx.x;
    for (int i = t; i < 96 * 32; i += 256) sW[i] = W[i];
    if (t < 32) sb[t] = b[t];
    __syncthreads();
    int node = blockIdx.x * 8 + threadIdx.y;
    if (node >= n) return;
    int col = threadIdx.x;
    float s = sb[col];
    const float* x0 = X0 + (size_t)node * ND;
    const float* x1 = X1 + (size_t)node * ND;
    const float* x2 = X2 + (size_t)node * ND;
#pragma unroll
    for (int j = 0; j < 32; j++) s += x0[j] * sW[j * 32 + col];
#pragma unroll
    for (int j = 0; j < 32; j++) s += x1[j] * sW[(32 + j) * 32 + col];
#pragma unroll
    for (int j = 0; j < 32; j++) s += x2[j] * sW[(64 + j) * 32 + col];
    s = leaky(s, 0.01f);
    out[(size_t)node * ND + col] = s;
    if (Tout) Tout[(size_t)node * ND + col] = s * dinv[node];
}

// fs = h@Ws+bs ; fd = h@Wd+bd ; ft = 0
__global__ void k_fsfd(const float* __restrict__ h, const float* __restrict__ Ws,
                       const float* __restrict__ bs, const float* __restrict__ Wd,
                       const float* __restrict__ bd, float* __restrict__ fs,
                       float* __restrict__ fd, float* __restrict__ ft, int n) {
    __shared__ float sWs[32 * 32], sWd[32 * 32], sbs[32], sbd[32];
    int t = threadIdx.y * 32 + threadIdx.x;
    for (int i = t; i < 1024; i += 256) { sWs[i] = Ws[i]; sWd[i] = Wd[i]; }
    if (t < 32) { sbs[t] = bs[t]; sbd[t] = bd[t]; }
    __syncthreads();
    int node = blockIdx.x * 8 + threadIdx.y;
    if (node >= n) return;
    int col = threadIdx.x;
    float a = sbs[col], c = sbd[col];
    const float* hr = h + (size_t)node * ND;
#pragma unroll
    for (int j = 0; j < 32; j++) {
        float x = hr[j];
        a += x * sWs[j * 32 + col];
        c += x * sWd[j * 32 + col];
    }
    fs[(size_t)node * ND + col] = a;
    fd[(size_t)node * ND + col] = c;
    ft[(size_t)node * ND + col] = 0.0f;
}

// logits[e] = sum_d leaky(fs[src]+fd[dst],0.2)*attn[d]; segmax via encoded atomicMax
// 8 threads per edge, float4 per thread
__global__ void k_logits(const int* __restrict__ src, const int* __restrict__ dst,
                         const float4* __restrict__ fs, const float4* __restrict__ fd,
                         const float4* __restrict__ attn, float* __restrict__ logits,
                         unsigned* __restrict__ segmax, int E) {
    long t = (long)blockIdx.x * blockDim.x + threadIdx.x;
    int e = (int)(t >> 3);
    if (e >= E) return;
    int lane = (int)(t & 7);
    int s = src[e], d = dst[e];
    float4 a = fs[(size_t)s * 8 + lane];
    float4 b = fd[(size_t)d * 8 + lane];
    float4 w = attn[lane];
    float v = leaky(a.x + b.x, 0.2f) * w.x + leaky(a.y + b.y, 0.2f) * w.y +
              leaky(a.z + b.z, 0.2f) * w.z + leaky(a.w + b.w, 0.2f) * w.w;
    v += __shfl_down_sync(0xffffffffu, v, 4, 8);
    v += __shfl_down_sync(0xffffffffu, v, 2, 8);
    v += __shfl_down_sync(0xffffffffu, v, 1, 8);
    if (lane == 0) {
        logits[e] = v;
        atomicMax(&segmax[d], enc_f(v));
    }
}

// ex[e] = exp(logits[e]-m[dst]); denom[dst] += ex
__global__ void k_exp(const int* __restrict__ dst, const float* __restrict__ logits,
                      const unsigned* __restrict__ segmax, float* __restrict__ ex,
                      float* __restrict__ denom, int E) {
    int e = blockIdx.x * blockDim.x + threadIdx.x;
    if (e >= E) return;
    int d = dst[e];
    float m = dec_f(segmax[d]);
    float v = expf(logits[e] - m);
    ex[e] = v;
    atomicAdd(&denom[d], v);
}

// ft[dst] += fs[src] * (ex[e]/denom[dst])    (8 threads/edge, vector RED)
__global__ void k_aggr(const int* __restrict__ src, const int* __restrict__ dst,
                       const float4* __restrict__ fs, const float* __restrict__ ex,
                       const float* __restrict__ denom, float* __restrict__ ft, int E) {
    long t = (long)blockIdx.x * blockDim.x + threadIdx.x;
    int e = (int)(t >> 3);
    if (e >= E) return;
    int lane = (int)(t & 7);
    int s = src[e], d = dst[e];
    float a = ex[e] / denom[d];
    float4 v = fs[(size_t)s * 8 + lane];
    v.x *= a; v.y *= a; v.z *= a; v.w *= a;
    red_v4(ft + (size_t)d * ND + lane * 4, v);
}

__global__ void k_out(const float4* __restrict__ ft, float4* __restrict__ out, int n) {
    int i = blockIdx.x * blockDim.x + threadIdx.x;
    if (i >= n * 8) return;
    float4 v = ft[i];
    v.x = leaky(v.x, 0.01f); v.y = leaky(v.y, 0.01f);
    v.z = leaky(v.z, 0.01f); v.w = leaky(v.w, 0.01f);
    out[i] = v;
}

// ---------------------------------------------------------------------------
// launch
// ---------------------------------------------------------------------------
extern "C" void kernel_launch(void* const* d_in, const int* in_sizes, int n_in,
                              void* d_out, int out_size) {
    const int*   src  = (const int*)d_in[0];
    const int*   dst  = (const int*)d_in[1];
    const float* emb  = (const float*)d_in[2];
    const float* lam  = (const float*)d_in[3];
    const float* chW  = (const float*)d_in[4];
    const float* chb  = (const float*)d_in[5];
    const float* Ws   = (const float*)d_in[6];
    const float* bs   = (const float*)d_in[7];
    const float* Wd   = (const float*)d_in[8];
    const float* bd   = (const float*)d_in[9];
    const float* attn = (const float*)d_in[10];

    const int E = in_sizes[0];
    const int n = in_sizes[2] / ND;

    float* base = nullptr;
    cudaGetSymbolAddress((void**)&base, g_buf);

    float* acc    = base;
    float* T      = base + 1 * SLOT;
    float* X1     = base + 2 * SLOT;
    float* X2     = base + 3 * SLOT;
    float* h1     = base + 4 * SLOT;
    float* h2     = base + 5 * SLOT;
    float* fs     = base + 6 * SLOT;
    float* fd     = base + 7 * SLOT;
    float* ft     = base + 8 * SLOT;
    float* logits = base + 9 * SLOT;
    float* exb    = logits + MAXE;
    float* nodes  = exb + MAXE;
    int*      deg    = (int*)nodes;
    unsigned* segmax = (unsigned*)(nodes + MAXN);
    float*    denom  = nodes + 2 * MAXN;
    float*    dinv   = nodes + 3 * MAXN;

    const int nt = 256;
    auto g = [&](long x) { return (int)((x + nt - 1) / nt); };
    const int gV4   = g((long)n * 8);     // float4 elements over node features
    const int gE8   = g((long)E * 8);     // 8 threads per edge
    const int gEdge = g((long)E);
    const int gLin  = (n + 7) / 8;
    dim3 blin(32, 8);

    // --- degrees + zero node scalars (deg, segmax, denom) ---
    k_zero<<<g(3 * MAXN), nt>>>(nodes, 3 * MAXN);
    k_deg<<<gEdge, nt>>>(dst, deg, E);
    k_dinv<<<g(n), nt>>>(deg, dinv, n);

    // --- ChebConv 1 (input = embedding) ---
    k_prescale<<<gV4, nt>>>((const float4*)emb, dinv, (float4*)T, (float4*)acc, n);
    k_gather<<<gE8, nt>>>(src, dst, (const float4*)T, acc, E);
    k_X1<<<gV4, nt>>>((float4*)acc, (const float4*)emb, dinv, lam, (float4*)X1, (float4*)T, n);
    k_gather<<<gE8, nt>>>(src, dst, (const float4*)T, acc, E);
    k_X2<<<gV4, nt>>>((float4*)acc, (const float4*)X1, (const float4*)emb, dinv, lam, (float4*)X2, n);
    k_cheb_linear<<<gLin, blin>>>(emb, X1, X2, chW, chb, dinv, h1, T, n); // T = h1*dinv

    // --- ChebConv 2 (input = h1; T already = h1*dinv, acc zeroed by k_X2) ---
    k_gather<<<gE8, nt>>>(src, dst, (const float4*)T, acc, E);
    k_X1<<<gV4, nt>>>((float4*)acc, (const float4*)h1, dinv, lam, (float4*)X1, (float4*)T, n);
    k_gather<<<gE8, nt>>>(src, dst, (const float4*)T, acc, E);
    k_X2<<<gV4, nt>>>((float4*)acc, (const float4*)X1, (const float4*)h1, dinv, lam, (float4*)X2, n);
    k_cheb_linear<<<gLin, blin>>>(h1, X1, X2, chW, chb, dinv, h2, nullptr, n);

    // --- GATv2 ---
    k_fsfd<<<gLin, blin>>>(h2, Ws, bs, Wd, bd, fs, fd, ft, n);
    k_logits<<<gE8, nt>>>(src, dst, (const float4*)fs, (const float4*)fd,
                          (const float4*)attn, logits, segmax, E);
    k_exp<<<gEdge, nt>>>(dst, logits, segmax, exb, denom, E);
    k_aggr<<<gE8, nt>>>(src, dst, (const float4*)fs, exb, denom, ft, E);
    k_out<<<gV4, nt>>>((const float4*)ft, (float4*)d_out, n);
}

// round 3
// speedup vs baseline: 2.3951x; 1.1563x over previous
#include <cuda_runtime.h>

#define ND 32
#define MAXN 100000
#define MAXE 1600000

static constexpr size_t SLOT = (size_t)MAXN * ND;

// Scratch arena (floats):
//  T0,T1,X1,X2,h1,h2,fs,fd : 8 * SLOT
//  logit_c : MAXE
//  csr_src : MAXE (int)
//  tail    : deg(N int), row_start(N+1 int), cursor(N int), dinv(N f), segmax(N f), blk(1024 int)
__device__ float g_buf[8 * SLOT + 2 * (size_t)MAXE + 6 * (size_t)MAXN + 2048];

__device__ __forceinline__ float leaky(float x, float s) {
    return x > 0.0f ? x : s * x;
}

// ---------------------------------------------------------------------------
// degree + scan + CSR fill
// ---------------------------------------------------------------------------
__global__ void k_zero_i(int* __restrict__ p, int n) {
    int i = blockIdx.x * blockDim.x + threadIdx.x;
    if (i < n) p[i] = 0;
}

__global__ void k_deg(const int* __restrict__ dst, int* __restrict__ deg, int E) {
    int e = blockIdx.x * blockDim.x + threadIdx.x;
    if (e < E) atomicAdd(&deg[dst[e]], 1);
}

__global__ void k_dinv(const int* __restrict__ deg, float* __restrict__ dinv, int n) {
    int i = blockIdx.x * blockDim.x + threadIdx.x;
    if (i < n) dinv[i] = rsqrtf(fmaxf((float)deg[i], 1.0f));
}

// per-block exclusive scan (1024/block), block totals to blk[]
__global__ void k_scan1(const int* __restrict__ deg, int* __restrict__ rs,
                        int* __restrict__ blk, int n) {
    __shared__ int sh[1024];
    int i = blockIdx.x * 1024 + threadIdx.x;
    int v = (i < n) ? deg[i] : 0;
    sh[threadIdx.x] = v;
    __syncthreads();
#pragma unroll
    for (int o = 1; o < 1024; o <<= 1) {
        int t = (threadIdx.x >= o) ? sh[threadIdx.x - o] : 0;
        __syncthreads();
        sh[threadIdx.x] += t;
        __syncthreads();
    }
    if (i < n) rs[i] = sh[threadIdx.x] - v;  // exclusive
    if (threadIdx.x == 1023) blk[blockIdx.x] = sh[1023];
}

__global__ void k_scan2(int* __restrict__ blk, int nb) {
    if (threadIdx.x == 0 && blockIdx.x == 0) {
        int run = 0;
        for (int b = 0; b < nb; b++) { int t = blk[b]; blk[b] = run; run += t; }
    }
}

__global__ void k_scan3(int* __restrict__ rs, int* __restrict__ cursor,
                        const int* __restrict__ blk, int n, int E) {
    int i = blockIdx.x * blockDim.x + threadIdx.x;
    if (i < n) {
        int v = rs[i] + blk[i >> 10];
        rs[i] = v;
        cursor[i] = v;
    }
    if (i == 0) rs[n] = E;
}

__global__ void k_fill(const int* __restrict__ src, const int* __restrict__ dst,
                       int* __restrict__ cursor, int* __restrict__ csr_src, int E) {
    int e = blockIdx.x * blockDim.x + threadIdx.x;
    if (e >= E) return;
    int p = atomicAdd(&cursor[dst[e]], 1);
    csr_src[p] = src[e];
}

// ---------------------------------------------------------------------------
// node-parallel elementwise / GEMM kernels
// ---------------------------------------------------------------------------
// T0 = f * dinv
__global__ void k_prescale(const float4* __restrict__ f, const float* __restrict__ dinv,
                           float4* __restrict__ T, int n) {
    int i = blockIdx.x * blockDim.x + threadIdx.x;
    if (i >= n * 8) return;
    float dv = dinv[i >> 3];
    float4 v = f[i];
    v.x *= dv; v.y *= dv; v.z *= dv; v.w *= dv;
    T[i] = v;
}

// warp per node: acc = sum_e Tin[csr_src[e]]; X1 = -r*acc*dv + (r-1)*f; Tout = X1*dv
__global__ void k_chebA(const int* __restrict__ rs, const int* __restrict__ csr_src,
                        const float* __restrict__ Tin, const float* __restrict__ f,
                        const float* __restrict__ dinv, const float* __restrict__ lam,
                        float* __restrict__ X1, float* __restrict__ Tout, int n) {
    int v = blockIdx.x * 8 + threadIdx.y;
    if (v >= n) return;
    int lane = threadIdx.x;
    int beg = rs[v], end = rs[v + 1];
    float acc = 0.0f;
    int p = beg;
    for (; p + 2 <= end; p += 2) {
        int s0 = csr_src[p], s1 = csr_src[p + 1];
        acc += Tin[(size_t)s0 * ND + lane];
        acc += Tin[(size_t)s1 * ND + lane];
    }
    if (p < end) acc += Tin[(size_t)csr_src[p] * ND + lane];
    float r = 2.0f / lam[0];
    float dv = dinv[v];
    float x1 = -r * acc * dv + (r - 1.0f) * f[(size_t)v * ND + lane];
    X1[(size_t)v * ND + lane] = x1;
    Tout[(size_t)v * ND + lane] = x1 * dv;
}

// warp per node: acc = sum_e Tin[csr]; X2 = -2r*acc*dv + 2(r-1)*X1 - f
__global__ void k_chebB(const int* __restrict__ rs, const int* __restrict__ csr_src,
                        const float* __restrict__ Tin, const float* __restrict__ X1,
                        const float* __restrict__ f, const float* __restrict__ dinv,
                        const float* __restrict__ lam, float* __restrict__ X2, int n) {
    int v = blockIdx.x * 8 + threadIdx.y;
    if (v >= n) return;
    int lane = threadIdx.x;
    int beg = rs[v], end = rs[v + 1];
    float acc = 0.0f;
    int p = beg;
    for (; p + 2 <= end; p += 2) {
        int s0 = csr_src[p], s1 = csr_src[p + 1];
        acc += Tin[(size_t)s0 * ND + lane];
        acc += Tin[(size_t)s1 * ND + lane];
    }
    if (p < end) acc += Tin[(size_t)csr_src[p] * ND + lane];
    float r = 2.0f / lam[0];
    float dv = dinv[v];
    X2[(size_t)v * ND + lane] = -2.0f * r * acc * dv +
                                2.0f * (r - 1.0f) * X1[(size_t)v * ND + lane] -
                                f[(size_t)v * ND + lane];
}

// out = leaky_relu([X0,X1,X2] @ W + b, 0.01); optionally Tout = out*dinv
__global__ void k_cheb_linear(const float* __restrict__ X0, const float* __restrict__ X1,
                              const float* __restrict__ X2, const float* __restrict__ W,
                              const float* __restrict__ b, const float* __restrict__ dinv,
                              float* __restrict__ out, float* __restrict__ Tout, int n) {
    __shared__ float sW[96 * 32];
    __shared__ float sb[32];
    int t = threadIdx.y * 32 + threadIdx.x;
    for (int i = t; i < 96 * 32; i += 256) sW[i] = W[i];
    if (t < 32) sb[t] = b[t];
    __syncthreads();
    int node = blockIdx.x * 8 + threadIdx.y;
    if (node >= n) return;
    int col = threadIdx.x;
    float s = sb[col];
    const float* x0 = X0 + (size_t)node * ND;
    const float* x1 = X1 + (size_t)node * ND;
    const float* x2 = X2 + (size_t)node * ND;
#pragma unroll
    for (int j = 0; j < 32; j++) s += x0[j] * sW[j * 32 + col];
#pragma unroll
    for (int j = 0; j < 32; j++) s += x1[j] * sW[(32 + j) * 32 + col];
#pragma unroll
    for (int j = 0; j < 32; j++) s += x2[j] * sW[(64 + j) * 32 + col];
    s = leaky(s, 0.01f);
    out[(size_t)node * ND + col] = s;
    if (Tout) Tout[(size_t)node * ND + col] = s * dinv[node];
}

// fs = h@Ws+bs ; fd = h@Wd+bd
__global__ void k_fsfd(const float* __restrict__ h, const float* __restrict__ Ws,
                       const float* __restrict__ bs, const float* __restrict__ Wd,
                       const float* __restrict__ bd, float* __restrict__ fs,
                       float* __restrict__ fd, int n) {
    __shared__ float sWs[32 * 32], sWd[32 * 32], sbs[32], sbd[32];
    int t = threadIdx.y * 32 + threadIdx.x;
    for (int i = t; i < 1024; i += 256) { sWs[i] = Ws[i]; sWd[i] = Wd[i]; }
    if (t < 32) { sbs[t] = bs[t]; sbd[t] = bd[t]; }
    __syncthreads();
    int node = blockIdx.x * 8 + threadIdx.y;
    if (node >= n) return;
    int col = threadIdx.x;
    float a = sbs[col], c = sbd[col];
    const float* hr = h + (size_t)node * ND;
#pragma unroll
    for (int j = 0; j < 32; j++) {
        float x = hr[j];
        a += x * sWs[j * 32 + col];
        c += x * sWd[j * 32 + col];
    }
    fs[(size_t)node * ND + col] = a;
    fd[(size_t)node * ND + col] = c;
}

// warp per node: per-edge logits (CSR order) + running max -> segmax (no atomics)
__global__ void k_gat1(const int* __restrict__ rs, const int* __restrict__ csr_src,
                       const float* __restrict__ fs, const float* __restrict__ fd,
                       const float* __restrict__ attn, float* __restrict__ logit_c,
                       float* __restrict__ segmax, int n) {
    int v = blockIdx.x * 8 + threadIdx.y;
    if (v >= n) return;
    int lane = threadIdx.x;
    int beg = rs[v], end = rs[v + 1];
    float fdv = fd[(size_t)v * ND + lane];
    float aw = attn[lane];
    float m = -3.0e38f;
    for (int p = beg; p < end; p++) {
        int s = csr_src[p];
        float t = fs[(size_t)s * ND + lane] + fdv;
        t = leaky(t, 0.2f) * aw;
#pragma unroll
        for (int o = 16; o; o >>= 1) t += __shfl_xor_sync(0xffffffffu, t, o);
        if (lane == 0) logit_c[p] = t;
        m = fmaxf(m, t);
    }
    if (lane == 0) segmax[v] = m;
}

// warp per node: softmax + weighted aggregation + final leaky, direct to d_out
__global__ void k_gat2(const int* __restrict__ rs, const int* __restrict__ csr_src,
                       const float* __restrict__ fs, const float* __restrict__ logit_c,
                       const float* __restrict__ segmax, float* __restrict__ out, int n) {
    int v = blockIdx.x * 8 + threadIdx.y;
    if (v >= n) return;
    int lane = threadIdx.x;
    int beg = rs[v], end = rs[v + 1];
    float m = segmax[v];
    float acc = 0.0f, den = 0.0f;
    for (int base = beg; base < end; base += 32) {
        int p = base + lane;
        bool valid = p < end;
        int s = valid ? csr_src[p] : 0;
        float ex = valid ? expf(logit_c[p] - m) : 0.0f;
        den += ex;
        int cnt = min(32, end - base);
        for (int j = 0; j < cnt; j++) {
            float exj = __shfl_sync(0xffffffffu, ex, j);
            int sj = __shfl_sync(0xffffffffu, s, j);
            acc += fs[(size_t)sj * ND + lane] * exj;
        }
    }
#pragma unroll
    for (int o = 16; o; o >>= 1) den += __shfl_xor_sync(0xffffffffu, den, o);
    float o = (den > 0.0f) ? leaky(acc / den, 0.01f) : 0.0f;
    out[(size_t)v * ND + lane] = o;
}

// ---------------------------------------------------------------------------
// launch
// ---------------------------------------------------------------------------
extern "C" void kernel_launch(void* const* d_in, const int* in_sizes, int n_in,
                              void* d_out, int out_size) {
    const int*   src  = (const int*)d_in[0];
    const int*   dst  = (const int*)d_in[1];
    const float* emb  = (const float*)d_in[2];
    const float* lam  = (const float*)d_in[3];
    const float* chW  = (const float*)d_in[4];
    const float* chb  = (const float*)d_in[5];
    const float* Ws   = (const float*)d_in[6];
    const float* bs   = (const float*)d_in[7];
    const float* Wd   = (const float*)d_in[8];
    const float* bd   = (const float*)d_in[9];
    const float* attn = (const float*)d_in[10];

    const int E = in_sizes[0];
    const int n = in_sizes[2] / ND;

    float* base = nullptr;
    cudaGetSymbolAddress((void**)&base, g_buf);

    float* T0      = base;
    float* T1      = base + 1 * SLOT;
    float* X1      = base + 2 * SLOT;
    float* X2      = base + 3 * SLOT;
    float* h1      = base + 4 * SLOT;
    float* h2      = base + 5 * SLOT;
    float* fs      = base + 6 * SLOT;
    float* fd      = base + 7 * SLOT;
    float* logit_c = base + 8 * SLOT;
    int*   csr_src = (int*)(logit_c + MAXE);
    float* tail    = logit_c + 2 * (size_t)MAXE;
    int*   deg     = (int*)tail;
    int*   rs      = (int*)(tail + MAXN);          // N+1
    int*   cursor  = (int*)(tail + 2 * MAXN + 64);
    float* dinv    = tail + 3 * MAXN + 64;
    float* segmax  = tail + 4 * MAXN + 64;
    int*   blk     = (int*)(tail + 5 * MAXN + 64); // scan block sums

    const int nt = 256;
    auto g = [&](long x) { return (int)((x + nt - 1) / nt); };
    const int gV4   = g((long)n * 8);
    const int gEdge = g((long)E);
    const int gNW   = (n + 7) / 8;  // warp-per-node kernels
    dim3 bNW(32, 8);
    const int nb = (n + 1023) / 1024;

    // --- CSR build ---
    k_zero_i<<<g(n), nt>>>(deg, n);
    k_deg<<<gEdge, nt>>>(dst, deg, E);
    k_dinv<<<g(n), nt>>>(deg, dinv, n);
    k_scan1<<<nb, 1024>>>(deg, rs, blk, n);
    k_scan2<<<1, 32>>>(blk, nb);
    k_scan3<<<g(n), nt>>>(rs, cursor, blk, n, E);
    k_fill<<<gEdge, nt>>>(src, dst, cursor, csr_src, E);

    // --- ChebConv 1 (input = embedding) ---
    k_prescale<<<gV4, nt>>>((const float4*)emb, dinv, (float4*)T0, n);
    k_chebA<<<gNW, bNW>>>(rs, csr_src, T0, emb, dinv, lam, X1, T1, n);
    k_chebB<<<gNW, bNW>>>(rs, csr_src, T1, X1, emb, dinv, lam, X2, n);
    k_cheb_linear<<<gNW, bNW>>>(emb, X1, X2, chW, chb, dinv, h1, T0, n); // T0 = h1*dinv

    // --- ChebConv 2 (input = h1) ---
    k_chebA<<<gNW, bNW>>>(rs, csr_src, T0, h1, dinv, lam, X1, T1, n);
    k_chebB<<<gNW, bNW>>>(rs, csr_src, T1, X1, h1, dinv, lam, X2, n);
    k_cheb_linear<<<gNW, bNW>>>(h1, X1, X2, chW, chb, dinv, h2, nullptr, n);

    // --- GATv2 ---
    k_fsfd<<<gNW, bNW>>>(h2, Ws, bs, Wd, bd, fs, fd, n);
    k_gat1<<<gNW, bNW>>>(rs, csr_src, fs, fd, attn, logit_c, segmax, n);
    k_gat2<<<gNW, bNW>>>(rs, csr_src, fs, logit_c, segmax, (float*)d_out, n);
}